// round 1
// baseline (speedup 1.0000x reference)
#include <cuda_runtime.h>
#include <math.h>

#define LSEQ 2048
#define BATCH 2
#define EMB 512
#define NH 8
#define HD 64
#define NHEAD 16  // BATCH*NH

// Scratch (device globals; allocation-free per harness rules)
__device__ __align__(16) float g_q[NHEAD * LSEQ * HD];
__device__ __align__(16) float g_k[NHEAD * LSEQ * HD];
__device__ __align__(16) float g_v[NHEAD * LSEQ * HD];
__device__ __align__(16) float g_o[NHEAD * LSEQ * HD];
__device__ __align__(16) float g_R[(size_t)NHEAD * LSEQ * LSEQ];  // 256 MiB

// ---------------------------------------------------------------------------
// Kernel 1: qkv = x @ W_in^T + b_in, scattered into head-major q (scaled), k, v
// C[r,c] = sum_e x[r,e] * W[c,e] + b[c];  M=4096, N=1536, K=512
// ---------------------------------------------------------------------------
__global__ void gemm_qkv(const float* __restrict__ x,
                         const float* __restrict__ W,
                         const float* __restrict__ bias) {
    __shared__ float As[16][65];
    __shared__ float Bs[16][65];
    const int tid = threadIdx.x;
    const int tx = tid & 15, ty = tid >> 4;
    const int r0 = blockIdx.x * 64;
    const int c0 = blockIdx.y * 64;
    const int lrow = tid >> 2;          // 0..63
    const int lk = (tid & 3) << 2;      // 0,4,8,12
    float acc[4][4] = {};
    for (int k0 = 0; k0 < EMB; k0 += 16) {
        float4 a = *(const float4*)(x + (size_t)(r0 + lrow) * EMB + k0 + lk);
        float4 b = *(const float4*)(W + (size_t)(c0 + lrow) * EMB + k0 + lk);
        As[lk + 0][lrow] = a.x; As[lk + 1][lrow] = a.y;
        As[lk + 2][lrow] = a.z; As[lk + 3][lrow] = a.w;
        Bs[lk + 0][lrow] = b.x; Bs[lk + 1][lrow] = b.y;
        Bs[lk + 2][lrow] = b.z; Bs[lk + 3][lrow] = b.w;
        __syncthreads();
#pragma unroll
        for (int k = 0; k < 16; k++) {
            float av[4], bv[4];
#pragma unroll
            for (int i = 0; i < 4; i++) av[i] = As[k][ty * 4 + i];
#pragma unroll
            for (int j = 0; j < 4; j++) bv[j] = Bs[k][tx * 4 + j];
#pragma unroll
            for (int i = 0; i < 4; i++)
#pragma unroll
                for (int j = 0; j < 4; j++) acc[i][j] += av[i] * bv[j];
        }
        __syncthreads();
    }
#pragma unroll
    for (int i = 0; i < 4; i++) {
#pragma unroll
        for (int j = 0; j < 4; j++) {
            int r = r0 + ty * 4 + i;
            int c = c0 + tx * 4 + j;
            float val = acc[i][j] + bias[c];
            int l = r >> 1, b = r & 1;
            int part = c >> 9;  // 0=q, 1=k, 2=v
            int cc = c & 511;
            int h = cc >> 6, d = cc & 63;
            size_t idx = ((size_t)(b * NH + h) * LSEQ + l) * HD + d;
            if (part == 0) g_q[idx] = val * 0.125f;  // D^-0.5
            else if (part == 1) g_k[idx] = val;
            else g_v[idx] = val;
        }
    }
}

// ---------------------------------------------------------------------------
// Kernel 2: R[h,l,m] = sum_d q[h,l,d] * Er[m,d]   (only m-tiles with m0 <= l0+63)
// ---------------------------------------------------------------------------
__global__ void gemm_rel(const float* __restrict__ Er) {
    const int l0 = blockIdx.x * 64;
    const int m0 = blockIdx.y * 64;
    if (m0 > l0 + 63) return;  // only lower-triangular band is ever read
    __shared__ float As[16][65];
    __shared__ float Bs[16][65];
    const int tid = threadIdx.x;
    const int tx = tid & 15, ty = tid >> 4;
    const int h = blockIdx.z;
    const float* q = g_q + (size_t)h * LSEQ * HD;
    const int lrow = tid >> 2;
    const int lk = (tid & 3) << 2;
    float acc[4][4] = {};
    for (int k0 = 0; k0 < HD; k0 += 16) {
        float4 a = *(const float4*)(q + (size_t)(l0 + lrow) * HD + k0 + lk);
        float4 b = *(const float4*)(Er + (size_t)(m0 + lrow) * HD + k0 + lk);
        As[lk + 0][lrow] = a.x; As[lk + 1][lrow] = a.y;
        As[lk + 2][lrow] = a.z; As[lk + 3][lrow] = a.w;
        Bs[lk + 0][lrow] = b.x; Bs[lk + 1][lrow] = b.y;
        Bs[lk + 2][lrow] = b.z; Bs[lk + 3][lrow] = b.w;
        __syncthreads();
#pragma unroll
        for (int k = 0; k < 16; k++) {
            float av[4], bv[4];
#pragma unroll
            for (int i = 0; i < 4; i++) av[i] = As[k][ty * 4 + i];
#pragma unroll
            for (int j = 0; j < 4; j++) bv[j] = Bs[k][tx * 4 + j];
#pragma unroll
            for (int i = 0; i < 4; i++)
#pragma unroll
                for (int j = 0; j < 4; j++) acc[i][j] += av[i] * bv[j];
        }
        __syncthreads();
    }
#pragma unroll
    for (int i = 0; i < 4; i++)
#pragma unroll
        for (int j = 0; j < 4; j++)
            g_R[((size_t)h * LSEQ + l0 + ty * 4 + i) * LSEQ + m0 + tx * 4 + j] = acc[i][j];
}

// ---------------------------------------------------------------------------
// Kernel 3: fused flash attention with rel-position add.
// scores[l,m] = q[l].k[m] + (m<=l ? R[h,l,2047-l+m] : 0); full (non-causal) softmax;
// o = softmax(scores) @ v. BM=BN=64, 256 threads, 4x4 per thread.
// ---------------------------------------------------------------------------
__global__ void flash_attn() {
    extern __shared__ float sm[];
    float* Qs = sm;               // [64][65]
    float* Ks = Qs + 64 * 65;     // [64][65]
    float* Vs = Ks + 64 * 65;     // [64][65]
    float* Ps = Vs + 64 * 65;     // [64][65]
    float* red = Ps + 64 * 65;    // [16][65]

    const int tid = threadIdx.x;
    const int tx = tid & 15, ty = tid >> 4;
    const int h = blockIdx.y;
    const int l0 = blockIdx.x * 64;
    const float* qg = g_q + (size_t)h * LSEQ * HD;
    const float* kg = g_k + (size_t)h * LSEQ * HD;
    const float* vg = g_v + (size_t)h * LSEQ * HD;
    const int lrow = tid >> 2;        // 0..63
    const int lc = (tid & 3) * 16;    // 0,16,32,48

    // load Q tile
#pragma unroll
    for (int u = 0; u < 4; u++) {
        float4 qv = *(const float4*)(qg + (size_t)(l0 + lrow) * HD + lc + u * 4);
        Qs[lrow * 65 + lc + u * 4 + 0] = qv.x;
        Qs[lrow * 65 + lc + u * 4 + 1] = qv.y;
        Qs[lrow * 65 + lc + u * 4 + 2] = qv.z;
        Qs[lrow * 65 + lc + u * 4 + 3] = qv.w;
    }

    float Mi[4], Si[4], O[4][4];
#pragma unroll
    for (int i = 0; i < 4; i++) {
        Mi[i] = -1e30f;
        Si[i] = 0.0f;
#pragma unroll
        for (int j = 0; j < 4; j++) O[i][j] = 0.0f;
    }

    for (int m0 = 0; m0 < LSEQ; m0 += 64) {
        __syncthreads();  // protect Ks/Vs/Ps from previous iteration's readers
#pragma unroll
        for (int u = 0; u < 4; u++) {
            float4 kv = *(const float4*)(kg + (size_t)(m0 + lrow) * HD + lc + u * 4);
            Ks[lrow * 65 + lc + u * 4 + 0] = kv.x;
            Ks[lrow * 65 + lc + u * 4 + 1] = kv.y;
            Ks[lrow * 65 + lc + u * 4 + 2] = kv.z;
            Ks[lrow * 65 + lc + u * 4 + 3] = kv.w;
            float4 vv = *(const float4*)(vg + (size_t)(m0 + lrow) * HD + lc + u * 4);
            Vs[lrow * 65 + lc + u * 4 + 0] = vv.x;
            Vs[lrow * 65 + lc + u * 4 + 1] = vv.y;
            Vs[lrow * 65 + lc + u * 4 + 2] = vv.z;
            Vs[lrow * 65 + lc + u * 4 + 3] = vv.w;
        }
        __syncthreads();

        // s = Q @ K^T
        float s[4][4] = {};
#pragma unroll
        for (int d = 0; d < 64; d++) {
            float av[4], bv[4];
#pragma unroll
            for (int i = 0; i < 4; i++) av[i] = Qs[(ty * 4 + i) * 65 + d];
#pragma unroll
            for (int j = 0; j < 4; j++) bv[j] = Ks[(tx * 4 + j) * 65 + d];
#pragma unroll
            for (int i = 0; i < 4; i++)
#pragma unroll
                for (int j = 0; j < 4; j++) s[i][j] += av[i] * bv[j];
        }

        // + skewed relative-position scores
#pragma unroll
        for (int i = 0; i < 4; i++) {
            int l = l0 + ty * 4 + i;
            const float* Rrow = g_R + ((size_t)h * LSEQ + l) * LSEQ;
#pragma unroll
            for (int j = 0; j < 4; j++) {
                int m = m0 + tx * 4 + j;
                if (m <= l) s[i][j] += Rrow[2047 - l + m];
            }
        }

        // tile row max, reduce across 16 tx threads
        float lm[4];
#pragma unroll
        for (int i = 0; i < 4; i++) {
            lm[i] = s[i][0];
#pragma unroll
            for (int j = 1; j < 4; j++) lm[i] = fmaxf(lm[i], s[i][j]);
            red[tx * 65 + ty * 4 + i] = lm[i];
        }
        __syncthreads();
        float newM[4], scale[4];
#pragma unroll
        for (int i = 0; i < 4; i++) {
            int row = ty * 4 + i;
            float tm = red[row];
#pragma unroll
            for (int t = 1; t < 16; t++) tm = fmaxf(tm, red[t * 65 + row]);
            newM[i] = fmaxf(Mi[i], tm);
            scale[i] = __expf(Mi[i] - newM[i]);
            Mi[i] = newM[i];
        }
        __syncthreads();  // red reuse

        // p = exp(s - newM), row sums
        float ls[4] = {0.f, 0.f, 0.f, 0.f};
#pragma unroll
        for (int i = 0; i < 4; i++) {
#pragma unroll
            for (int j = 0; j < 4; j++) {
                float p = __expf(s[i][j] - newM[i]);
                Ps[(ty * 4 + i) * 65 + tx * 4 + j] = p;
                ls[i] += p;
            }
            red[tx * 65 + ty * 4 + i] = ls[i];
        }
        __syncthreads();
#pragma unroll
        for (int i = 0; i < 4; i++) {
            int row = ty * 4 + i;
            float tsum = 0.f;
#pragma unroll
            for (int t = 0; t < 16; t++) tsum += red[t * 65 + row];
            Si[i] = Si[i] * scale[i] + tsum;
#pragma unroll
            for (int j = 0; j < 4; j++) O[i][j] *= scale[i];
        }

        // O += P @ V
#pragma unroll
        for (int mk = 0; mk < 64; mk++) {
            float av[4], bv[4];
#pragma unroll
            for (int i = 0; i < 4; i++) av[i] = Ps[(ty * 4 + i) * 65 + mk];
#pragma unroll
            for (int j = 0; j < 4; j++) bv[j] = Vs[mk * 65 + tx * 4 + j];
#pragma unroll
            for (int i = 0; i < 4; i++)
#pragma unroll
                for (int j = 0; j < 4; j++) O[i][j] += av[i] * bv[j];
        }
    }

#pragma unroll
    for (int i = 0; i < 4; i++) {
        float inv = 1.0f / Si[i];
#pragma unroll
        for (int j = 0; j < 4; j++)
            g_o[((size_t)h * LSEQ + l0 + ty * 4 + i) * HD + tx * 4 + j] = O[i][j] * inv;
    }
}

// ---------------------------------------------------------------------------
// Kernel 4: out = attn_out @ W_out^T + b_out   (gathering A from head-major g_o)
// M=4096, N=512, K=512
// ---------------------------------------------------------------------------
__global__ void gemm_out(const float* __restrict__ Wout,
                         const float* __restrict__ bout,
                         float* __restrict__ out) {
    __shared__ float As[16][65];
    __shared__ float Bs[16][65];
    const int tid = threadIdx.x;
    const int tx = tid & 15, ty = tid >> 4;
    const int r0 = blockIdx.x * 64;
    const int c0 = blockIdx.y * 64;
    const int lrow = tid >> 2;
    const int lk = (tid & 3) << 2;
    float acc[4][4] = {};
    for (int k0 = 0; k0 < EMB; k0 += 16) {
        int r = r0 + lrow;
        int e = k0 + lk;
        int l = r >> 1, b = r & 1;
        int hh = e >> 6, d = e & 63;
        float4 a = *(const float4*)(g_o + ((size_t)(b * NH + hh) * LSEQ + l) * HD + d);
        float4 bb = *(const float4*)(Wout + (size_t)(c0 + lrow) * EMB + k0 + lk);
        As[lk + 0][lrow] = a.x; As[lk + 1][lrow] = a.y;
        As[lk + 2][lrow] = a.z; As[lk + 3][lrow] = a.w;
        Bs[lk + 0][lrow] = bb.x; Bs[lk + 1][lrow] = bb.y;
        Bs[lk + 2][lrow] = bb.z; Bs[lk + 3][lrow] = bb.w;
        __syncthreads();
#pragma unroll
        for (int k = 0; k < 16; k++) {
            float av[4], bv[4];
#pragma unroll
            for (int i = 0; i < 4; i++) av[i] = As[k][ty * 4 + i];
#pragma unroll
            for (int j = 0; j < 4; j++) bv[j] = Bs[k][tx * 4 + j];
#pragma unroll
            for (int i = 0; i < 4; i++)
#pragma unroll
                for (int j = 0; j < 4; j++) acc[i][j] += av[i] * bv[j];
        }
        __syncthreads();
    }
#pragma unroll
    for (int i = 0; i < 4; i++)
#pragma unroll
        for (int j = 0; j < 4; j++) {
            int r = r0 + ty * 4 + i;
            int c = c0 + tx * 4 + j;
            out[(size_t)r * EMB + c] = acc[i][j] + bout[c];
        }
}

// ---------------------------------------------------------------------------
extern "C" void kernel_launch(void* const* d_in, const int* in_sizes, int n_in,
                              void* d_out, int out_size) {
    (void)in_sizes; (void)n_in; (void)out_size;
    const float* x    = (const float*)d_in[0];
    const float* Win  = (const float*)d_in[1];
    const float* bin  = (const float*)d_in[2];
    const float* Wout = (const float*)d_in[3];
    const float* bout = (const float*)d_in[4];
    const float* Er   = (const float*)d_in[5];
    float* out = (float*)d_out;

    gemm_qkv<<<dim3(64, 24), 256>>>(x, Win, bin);
    gemm_rel<<<dim3(32, 32, 16), 256>>>(Er);

    size_t flash_smem = (4 * 64 * 65 + 16 * 65) * sizeof(float);  // 70720 B
    cudaFuncSetAttribute(flash_attn, cudaFuncAttributeMaxDynamicSharedMemorySize,
                         (int)flash_smem);
    flash_attn<<<dim3(32, 16), 256, flash_smem>>>();

    gemm_out<<<dim3(64, 8), 256>>>(Wout, bout, out);
}

// round 3
// speedup vs baseline: 2.3611x; 2.3611x over previous
#include <cuda_runtime.h>
#include <math.h>
#include <stdint.h>

#define LSEQ 2048
#define BATCH 2
#define EMB 512
#define NH 8
#define HD 64
#define NHEAD 16  // BATCH*NH

// Scratch (device globals; allocation-free per harness rules)
__device__ __align__(16) float g_q[NHEAD * LSEQ * HD];
__device__ __align__(16) float g_k[NHEAD * LSEQ * HD];
__device__ __align__(16) float g_v[NHEAD * LSEQ * HD];
__device__ __align__(16) float g_o[NHEAD * LSEQ * HD];
__device__ __align__(16) float g_R[(size_t)NHEAD * LSEQ * LSEQ];  // 256 MiB

__device__ __forceinline__ float to_tf32(float x) {
    uint32_t y;
    asm("cvt.rna.tf32.f32 %0, %1;" : "=r"(y) : "f"(x));
    return __uint_as_float(y);
}

__device__ __forceinline__ void mma8(float d[4], uint32_t a0, uint32_t a1,
                                     uint32_t a2, uint32_t a3,
                                     uint32_t b0, uint32_t b1) {
    asm volatile(
        "mma.sync.aligned.m16n8k8.row.col.f32.tf32.tf32.f32 "
        "{%0,%1,%2,%3}, {%4,%5,%6,%7}, {%8,%9}, {%0,%1,%2,%3};\n"
        : "+f"(d[0]), "+f"(d[1]), "+f"(d[2]), "+f"(d[3])
        : "r"(a0), "r"(a1), "r"(a2), "r"(a3), "r"(b0), "r"(b1));
}

// BK=16 mma micro-tile: As[m][k] stride 20, Bs[n][k] stride 20.
// Warp computes 16 rows (mbase) x 64 cols into acc[8][4].
__device__ __forceinline__ void mma_block16(const float* As, const float* Bs,
                                            float acc[8][4], int lane, int mbase) {
#pragma unroll
    for (int ks = 0; ks < 2; ks++) {
        const float* ap = As + (mbase + (lane >> 2)) * 20 + ks * 8 + (lane & 3);
        uint32_t a0 = __float_as_uint(ap[0]);
        uint32_t a1 = __float_as_uint(ap[8 * 20]);
        uint32_t a2 = __float_as_uint(ap[4]);
        uint32_t a3 = __float_as_uint(ap[8 * 20 + 4]);
#pragma unroll
        for (int nc = 0; nc < 8; nc++) {
            const float* bp = Bs + (nc * 8 + (lane >> 2)) * 20 + ks * 8 + (lane & 3);
            mma8(acc[nc], a0, a1, a2, a3,
                 __float_as_uint(bp[0]), __float_as_uint(bp[4]));
        }
    }
}

// ---------------------------------------------------------------------------
// Kernel 1: qkv = x @ W_in^T + b_in, scattered head-major, q scaled. tf32 mma.
// BM=128, BN=64, BK=16, 256 threads (8 warps).
// ---------------------------------------------------------------------------
__global__ void __launch_bounds__(256) gemm_qkv(const float* __restrict__ x,
                                                const float* __restrict__ W,
                                                const float* __restrict__ bias) {
    __shared__ float As[128 * 20];
    __shared__ float Bs[64 * 20];
    const int tid = threadIdx.x;
    const int lane = tid & 31, warp = tid >> 5;
    const int r0 = blockIdx.x * 128;
    const int c0 = blockIdx.y * 64;
    float acc[8][4] = {};

    const int ai = tid >> 1, akp = (tid & 1) * 8;     // A: row, k-offset (2x float4)
    const int bn = tid >> 2, bkp = (tid & 3) * 4;     // B: row, k-offset (1x float4)

    for (int k0 = 0; k0 < EMB; k0 += 16) {
#pragma unroll
        for (int u = 0; u < 2; u++) {
            float4 a = *(const float4*)(x + (size_t)(r0 + ai) * EMB + k0 + akp + u * 4);
            float* d = As + ai * 20 + akp + u * 4;
            d[0] = to_tf32(a.x); d[1] = to_tf32(a.y);
            d[2] = to_tf32(a.z); d[3] = to_tf32(a.w);
        }
        {
            float4 b = *(const float4*)(W + (size_t)(c0 + bn) * EMB + k0 + bkp);
            float* d = Bs + bn * 20 + bkp;
            d[0] = to_tf32(b.x); d[1] = to_tf32(b.y);
            d[2] = to_tf32(b.z); d[3] = to_tf32(b.w);
        }
        __syncthreads();
        mma_block16(As, Bs, acc, lane, warp * 16);
        __syncthreads();
    }

    const int row_lo = r0 + warp * 16 + (lane >> 2);
#pragma unroll
    for (int nc = 0; nc < 8; nc++) {
#pragma unroll
        for (int j = 0; j < 4; j++) {
            int r = row_lo + (j >> 1) * 8;
            int c = c0 + nc * 8 + 2 * (lane & 3) + (j & 1);
            float val = acc[nc][j] + bias[c];
            int l = r >> 1, b = r & 1;
            int part = c >> 9;
            int cc = c & 511;
            int h = cc >> 6, d = cc & 63;
            size_t idx = ((size_t)(b * NH + h) * LSEQ + l) * HD + d;
            if (part == 0) g_q[idx] = val * 0.125f;
            else if (part == 1) g_k[idx] = val;
            else g_v[idx] = val;
        }
    }
}

// ---------------------------------------------------------------------------
// Kernel 2: R[h,l,m] = sum_d q[h,l,d] * Er[m,d]. Lower-band tiles only.
// ---------------------------------------------------------------------------
__global__ void __launch_bounds__(256) gemm_rel(const float* __restrict__ Er) {
    const int l0 = blockIdx.x * 128;
    const int m0 = blockIdx.y * 64;
    if (m0 > l0 + 127) return;
    __shared__ float As[128 * 20];
    __shared__ float Bs[64 * 20];
    const int tid = threadIdx.x;
    const int lane = tid & 31, warp = tid >> 5;
    const int h = blockIdx.z;
    const float* q = g_q + (size_t)h * LSEQ * HD;
    float acc[8][4] = {};

    const int ai = tid >> 1, akp = (tid & 1) * 8;
    const int bn = tid >> 2, bkp = (tid & 3) * 4;

    for (int k0 = 0; k0 < HD; k0 += 16) {
#pragma unroll
        for (int u = 0; u < 2; u++) {
            float4 a = *(const float4*)(q + (size_t)(l0 + ai) * HD + k0 + akp + u * 4);
            float* d = As + ai * 20 + akp + u * 4;
            d[0] = to_tf32(a.x); d[1] = to_tf32(a.y);
            d[2] = to_tf32(a.z); d[3] = to_tf32(a.w);
        }
        {
            float4 b = *(const float4*)(Er + (size_t)(m0 + bn) * HD + k0 + bkp);
            float* d = Bs + bn * 20 + bkp;
            d[0] = to_tf32(b.x); d[1] = to_tf32(b.y);
            d[2] = to_tf32(b.z); d[3] = to_tf32(b.w);
        }
        __syncthreads();
        mma_block16(As, Bs, acc, lane, warp * 16);
        __syncthreads();
    }

    const int row_lo = l0 + warp * 16 + (lane >> 2);
#pragma unroll
    for (int nc = 0; nc < 8; nc++) {
#pragma unroll
        for (int j = 0; j < 4; j++) {
            int l = row_lo + (j >> 1) * 8;
            int m = m0 + nc * 8 + 2 * (lane & 3) + (j & 1);
            g_R[((size_t)h * LSEQ + l) * LSEQ + m] = acc[nc][j];
        }
    }
}

// ---------------------------------------------------------------------------
// Kernel 3: fused flash attention + rel add (tf32 mma, non-causal softmax).
// BM=128 (8 warps x 16 rows), BN=64 key tiles. Each warp owns full rows.
// ---------------------------------------------------------------------------
__global__ void __launch_bounds__(256) flash_attn() {
    extern __shared__ float sm[];
    float* Qs = sm;                 // [128][68]
    float* Ks = Qs + 128 * 68;      // [64][68]
    float* Vs = Ks + 64 * 68;       // [64][72]  (stored [m][d])
    float* Ps = Vs + 64 * 72;       // [128][68]

    const int tid = threadIdx.x;
    const int lane = tid & 31, warp = tid >> 5;
    const int h = blockIdx.y;
    const int l0 = blockIdx.x * 128;
    const float* qg = g_q + (size_t)h * LSEQ * HD;
    const float* kg = g_k + (size_t)h * LSEQ * HD;
    const float* vg = g_v + (size_t)h * LSEQ * HD;

    // load Q tile (128x64), tf32
    {
        int row = tid >> 1, cb = (tid & 1) * 32;
#pragma unroll
        for (int u = 0; u < 8; u++) {
            float4 qv = *(const float4*)(qg + (size_t)(l0 + row) * HD + cb + u * 4);
            float* d = Qs + row * 68 + cb + u * 4;
            d[0] = to_tf32(qv.x); d[1] = to_tf32(qv.y);
            d[2] = to_tf32(qv.z); d[3] = to_tf32(qv.w);
        }
    }

    const int r_quad = lane >> 2;        // 0..7
    const int t4 = lane & 3;             // 0..3
    const int row_lo = warp * 16 + r_quad;   // local row (0..127)
    float Mi[2] = {-1e30f, -1e30f};
    float Si[2] = {0.f, 0.f};
    float o[8][4] = {};

    for (int m0 = 0; m0 < LSEQ; m0 += 64) {
        __syncthreads();
        // stage K and V tiles
        {
            int row = tid >> 2, cb = (tid & 3) * 16;
#pragma unroll
            for (int u = 0; u < 4; u++) {
                float4 kv = *(const float4*)(kg + (size_t)(m0 + row) * HD + cb + u * 4);
                float* d = Ks + row * 68 + cb + u * 4;
                d[0] = to_tf32(kv.x); d[1] = to_tf32(kv.y);
                d[2] = to_tf32(kv.z); d[3] = to_tf32(kv.w);
                float4 vv = *(const float4*)(vg + (size_t)(m0 + row) * HD + cb + u * 4);
                float* e = Vs + row * 72 + cb + u * 4;
                e[0] = to_tf32(vv.x); e[1] = to_tf32(vv.y);
                e[2] = to_tf32(vv.z); e[3] = to_tf32(vv.w);
            }
        }
        __syncthreads();

        // S = Q @ K^T   (16x64 per warp)
        float s[8][4] = {};
#pragma unroll
        for (int ks = 0; ks < 8; ks++) {
            const float* ap = Qs + (warp * 16 + r_quad) * 68 + ks * 8 + t4;
            uint32_t a0 = __float_as_uint(ap[0]);
            uint32_t a1 = __float_as_uint(ap[8 * 68]);
            uint32_t a2 = __float_as_uint(ap[4]);
            uint32_t a3 = __float_as_uint(ap[8 * 68 + 4]);
#pragma unroll
            for (int nc = 0; nc < 8; nc++) {
                const float* bp = Ks + (nc * 8 + r_quad) * 68 + ks * 8 + t4;
                mma8(s[nc], a0, a1, a2, a3,
                     __float_as_uint(bp[0]), __float_as_uint(bp[4]));
            }
        }

        // + relative-position scores (skewed gather from g_R)
#pragma unroll
        for (int i = 0; i < 2; i++) {
            int l = l0 + row_lo + i * 8;
            const float* Rrow = g_R + ((size_t)h * LSEQ + l) * LSEQ + (2047 - l);
#pragma unroll
            for (int nc = 0; nc < 8; nc++) {
                int m = m0 + nc * 8 + 2 * t4;
                if (m <= l) s[nc][2 * i] += Rrow[m];
                if (m + 1 <= l) s[nc][2 * i + 1] += Rrow[m + 1];
            }
        }

        // online softmax (rows fully warp-local; quad shfl reductions)
        float mloc[2] = {-1e30f, -1e30f};
#pragma unroll
        for (int nc = 0; nc < 8; nc++) {
            mloc[0] = fmaxf(mloc[0], fmaxf(s[nc][0], s[nc][1]));
            mloc[1] = fmaxf(mloc[1], fmaxf(s[nc][2], s[nc][3]));
        }
#pragma unroll
        for (int off = 1; off < 4; off <<= 1) {
            mloc[0] = fmaxf(mloc[0], __shfl_xor_sync(0xffffffffu, mloc[0], off));
            mloc[1] = fmaxf(mloc[1], __shfl_xor_sync(0xffffffffu, mloc[1], off));
        }
        float newM[2], sc[2], lsum[2] = {0.f, 0.f};
#pragma unroll
        for (int i = 0; i < 2; i++) {
            newM[i] = fmaxf(Mi[i], mloc[i]);
            sc[i] = __expf(Mi[i] - newM[i]);
            Mi[i] = newM[i];
        }
#pragma unroll
        for (int nc = 0; nc < 8; nc++) {
            float p0 = __expf(s[nc][0] - newM[0]);
            float p1 = __expf(s[nc][1] - newM[0]);
            float p2 = __expf(s[nc][2] - newM[1]);
            float p3 = __expf(s[nc][3] - newM[1]);
            lsum[0] += p0 + p1;
            lsum[1] += p2 + p3;
            float* pp = Ps + (warp * 16 + r_quad) * 68 + nc * 8 + 2 * t4;
            pp[0] = to_tf32(p0);
            pp[1] = to_tf32(p1);
            pp[8 * 68] = to_tf32(p2);
            pp[8 * 68 + 1] = to_tf32(p3);
        }
#pragma unroll
        for (int off = 1; off < 4; off <<= 1) {
            lsum[0] += __shfl_xor_sync(0xffffffffu, lsum[0], off);
            lsum[1] += __shfl_xor_sync(0xffffffffu, lsum[1], off);
        }
#pragma unroll
        for (int i = 0; i < 2; i++) Si[i] = Si[i] * sc[i] + lsum[i];
#pragma unroll
        for (int nc = 0; nc < 8; nc++) {
            o[nc][0] *= sc[0]; o[nc][1] *= sc[0];
            o[nc][2] *= sc[1]; o[nc][3] *= sc[1];
        }
        __syncwarp();  // Ps rows are warp-private: warp-level ordering suffices

        // O += P @ V   (A from Ps, B from Vs[m][d])
#pragma unroll
        for (int ks = 0; ks < 8; ks++) {
            const float* ap = Ps + (warp * 16 + r_quad) * 68 + ks * 8 + t4;
            uint32_t a0 = __float_as_uint(ap[0]);
            uint32_t a1 = __float_as_uint(ap[8 * 68]);
            uint32_t a2 = __float_as_uint(ap[4]);
            uint32_t a3 = __float_as_uint(ap[8 * 68 + 4]);
#pragma unroll
            for (int nc = 0; nc < 8; nc++) {
                const float* bp = Vs + (ks * 8 + t4) * 72 + nc * 8 + r_quad;
                mma8(o[nc], a0, a1, a2, a3,
                     __float_as_uint(bp[0]), __float_as_uint(bp[4 * 72]));
            }
        }
    }

    float inv[2] = {1.0f / Si[0], 1.0f / Si[1]};
#pragma unroll
    for (int nc = 0; nc < 8; nc++) {
#pragma unroll
        for (int j = 0; j < 4; j++) {
            int l = l0 + row_lo + (j >> 1) * 8;
            int d = nc * 8 + 2 * t4 + (j & 1);
            g_o[((size_t)h * LSEQ + l) * HD + d] = o[nc][j] * inv[j >> 1];
        }
    }
}

// ---------------------------------------------------------------------------
// Kernel 4: out = attn_out @ W_out^T + b_out (gather A from head-major g_o)
// ---------------------------------------------------------------------------
__global__ void __launch_bounds__(256) gemm_out(const float* __restrict__ Wout,
                                                const float* __restrict__ bout,
                                                float* __restrict__ out) {
    __shared__ float As[128 * 20];
    __shared__ float Bs[64 * 20];
    const int tid = threadIdx.x;
    const int lane = tid & 31, warp = tid >> 5;
    const int r0 = blockIdx.x * 128;
    const int c0 = blockIdx.y * 64;
    float acc[8][4] = {};

    const int ai = tid >> 1, akp = (tid & 1) * 8;
    const int bn = tid >> 2, bkp = (tid & 3) * 4;

    for (int k0 = 0; k0 < EMB; k0 += 16) {
        {
            int r = r0 + ai;
            int l = r >> 1, b = r & 1;
#pragma unroll
            for (int u = 0; u < 2; u++) {
                int e = k0 + akp + u * 4;
                int hh = e >> 6, d = e & 63;
                float4 a = *(const float4*)(g_o + ((size_t)(b * NH + hh) * LSEQ + l) * HD + d);
                float* dst = As + ai * 20 + akp + u * 4;
                dst[0] = to_tf32(a.x); dst[1] = to_tf32(a.y);
                dst[2] = to_tf32(a.z); dst[3] = to_tf32(a.w);
            }
        }
        {
            float4 bb = *(const float4*)(Wout + (size_t)(c0 + bn) * EMB + k0 + bkp);
            float* d = Bs + bn * 20 + bkp;
            d[0] = to_tf32(bb.x); d[1] = to_tf32(bb.y);
            d[2] = to_tf32(bb.z); d[3] = to_tf32(bb.w);
        }
        __syncthreads();
        mma_block16(As, Bs, acc, lane, warp * 16);
        __syncthreads();
    }

    const int row_lo = r0 + warp * 16 + (lane >> 2);
#pragma unroll
    for (int nc = 0; nc < 8; nc++) {
#pragma unroll
        for (int j = 0; j < 4; j++) {
            int r = row_lo + (j >> 1) * 8;
            int c = c0 + nc * 8 + 2 * (lane & 3) + (j & 1);
            out[(size_t)r * EMB + c] = acc[nc][j] + bout[c];
        }
    }
}

// ---------------------------------------------------------------------------
extern "C" void kernel_launch(void* const* d_in, const int* in_sizes, int n_in,
                              void* d_out, int out_size) {
    (void)in_sizes; (void)n_in; (void)out_size;
    const float* x    = (const float*)d_in[0];
    const float* Win  = (const float*)d_in[1];
    const float* bin  = (const float*)d_in[2];
    const float* Wout = (const float*)d_in[3];
    const float* bout = (const float*)d_in[4];
    const float* Er   = (const float*)d_in[5];
    float* out = (float*)d_out;

    gemm_qkv<<<dim3(32, 24), 256>>>(x, Win, bin);
    gemm_rel<<<dim3(16, 32, 16), 256>>>(Er);

    size_t flash_smem = (size_t)(128 * 68 + 64 * 68 + 64 * 72 + 128 * 68) * sizeof(float);
    cudaFuncSetAttribute(flash_attn, cudaFuncAttributeMaxDynamicSharedMemorySize,
                         (int)flash_smem);
    flash_attn<<<dim3(16, 16), 256, flash_smem>>>();

    gemm_out<<<dim3(32, 8), 256>>>(Wout, bout, out);
}

// round 4
// speedup vs baseline: 2.4855x; 1.0527x over previous
#include <cuda_runtime.h>
#include <math.h>
#include <stdint.h>

#define LSEQ 2048
#define BATCH 2
#define EMB 512
#define NH 8
#define HD 64
#define NHEAD 16  // BATCH*NH

// Scratch (device globals; allocation-free per harness rules)
__device__ __align__(16) float g_q[NHEAD * LSEQ * HD];
__device__ __align__(16) float g_k[NHEAD * LSEQ * HD];
__device__ __align__(16) float g_v[NHEAD * LSEQ * HD];
__device__ __align__(16) float g_o[NHEAD * LSEQ * HD];
__device__ __align__(16) float g_R[(size_t)NHEAD * LSEQ * LSEQ + 16];  // 256 MiB + pad

__device__ __forceinline__ float to_tf32(float x) {
    uint32_t y;
    asm("cvt.rna.tf32.f32 %0, %1;" : "=r"(y) : "f"(x));
    return __uint_as_float(y);
}

__device__ __forceinline__ void mma8(float d[4], uint32_t a0, uint32_t a1,
                                     uint32_t a2, uint32_t a3,
                                     uint32_t b0, uint32_t b1) {
    asm volatile(
        "mma.sync.aligned.m16n8k8.row.col.f32.tf32.tf32.f32 "
        "{%0,%1,%2,%3}, {%4,%5,%6,%7}, {%8,%9}, {%0,%1,%2,%3};\n"
        : "+f"(d[0]), "+f"(d[1]), "+f"(d[2]), "+f"(d[3])
        : "r"(a0), "r"(a1), "r"(a2), "r"(a3), "r"(b0), "r"(b1));
}

__device__ __forceinline__ void cp16(uint32_t dst, const void* src) {
    asm volatile("cp.async.cg.shared.global [%0], [%1], 16;\n" ::"r"(dst), "l"(src));
}
__device__ __forceinline__ void cp_commit() { asm volatile("cp.async.commit_group;\n"); }
__device__ __forceinline__ void cp_wait0() { asm volatile("cp.async.wait_group 0;\n" ::: "memory"); }
__device__ __forceinline__ void cp_wait1() { asm volatile("cp.async.wait_group 1;\n" ::: "memory"); }

#define GS (128 * 36)  // one GEMM stage (floats), stride 36 => conflict-free frags

// Shared GEMM compute: one BK=32 stage, 8 warps as 4(m)x2(n), warp tile 32x64.
__device__ __forceinline__ void gemm_stage(const float* A, const float* B,
                                           float acc[2][8][4], int wm, int wn,
                                           int rq, int t4) {
#pragma unroll
    for (int ks = 0; ks < 4; ks++) {
        uint32_t bf[8][2];
#pragma unroll
        for (int nf = 0; nf < 8; nf++) {
            const float* bp = B + (wn * 64 + nf * 8 + rq) * 36 + ks * 8 + t4;
            bf[nf][0] = __float_as_uint(bp[0]);
            bf[nf][1] = __float_as_uint(bp[4]);
        }
#pragma unroll
        for (int mf = 0; mf < 2; mf++) {
            const float* ap = A + (wm * 32 + mf * 16 + rq) * 36 + ks * 8 + t4;
            uint32_t a0 = __float_as_uint(ap[0]);
            uint32_t a1 = __float_as_uint(ap[8 * 36]);
            uint32_t a2 = __float_as_uint(ap[4]);
            uint32_t a3 = __float_as_uint(ap[8 * 36 + 4]);
#pragma unroll
            for (int nf = 0; nf < 8; nf++)
                mma8(acc[mf][nf], a0, a1, a2, a3, bf[nf][0], bf[nf][1]);
        }
    }
}

// ---------------------------------------------------------------------------
// Kernel 1: qkv = x @ W_in^T + b_in -> scatter head-major (q scaled, all tf32-
// rounded on store). M=4096, N=1536, K=512. BM=BN=128, BK=32, cp.async x2.
// ---------------------------------------------------------------------------
__global__ void __launch_bounds__(256) gemm_qkv(const float* __restrict__ x,
                                                const float* __restrict__ W,
                                                const float* __restrict__ bias) {
    extern __shared__ float sm[];
    float* As = sm;
    float* Bs = sm + 2 * GS;
    const int tid = threadIdx.x, lane = tid & 31, warp = tid >> 5;
    const int wm = warp >> 1, wn = warp & 1;
    const int rq = lane >> 2, t4 = lane & 3;
    const int r0 = blockIdx.x * 128, c0 = blockIdx.y * 128;
    const int arow = tid >> 3, achk = (tid & 7) * 4;
    uint32_t sA = (uint32_t)__cvta_generic_to_shared(As);
    uint32_t sB = (uint32_t)__cvta_generic_to_shared(Bs);
    float acc[2][8][4] = {};

    auto prefetch = [&](int st, int kt) {
        int k0 = kt * 32;
#pragma unroll
        for (int p = 0; p < 4; p++) {
            int row = p * 32 + arow;
            cp16(sA + (st * GS + row * 36 + achk) * 4,
                 x + (size_t)(r0 + row) * EMB + k0 + achk);
            cp16(sB + (st * GS + row * 36 + achk) * 4,
                 W + (size_t)(c0 + row) * EMB + k0 + achk);
        }
    };

    prefetch(0, 0);
    cp_commit();
    const int nk = EMB / 32;
    for (int kt = 0; kt < nk; kt++) {
        if (kt + 1 < nk) {
            prefetch((kt + 1) & 1, kt + 1);
            cp_commit();
            cp_wait1();
        } else {
            cp_wait0();
        }
        __syncthreads();
        gemm_stage(As + (kt & 1) * GS, Bs + (kt & 1) * GS, acc, wm, wn, rq, t4);
        __syncthreads();
    }

#pragma unroll
    for (int mf = 0; mf < 2; mf++)
#pragma unroll
        for (int nf = 0; nf < 8; nf++)
#pragma unroll
            for (int j = 0; j < 4; j++) {
                int r = r0 + wm * 32 + mf * 16 + rq + (j >> 1) * 8;
                int c = c0 + wn * 64 + nf * 8 + 2 * t4 + (j & 1);
                float val = acc[mf][nf][j] + bias[c];
                int l = r >> 1, b = r & 1;
                int part = c >> 9;
                int cc = c & 511;
                int h = cc >> 6, d = cc & 63;
                size_t idx = ((size_t)(b * NH + h) * LSEQ + l) * HD + d;
                if (part == 0) g_q[idx] = to_tf32(val) * 0.125f;
                else if (part == 1) g_k[idx] = to_tf32(val);
                else g_v[idx] = to_tf32(val);
            }
}

// ---------------------------------------------------------------------------
// Kernel 2: R[h,l,m] = q[h,l,:] . Er[m,:]. K=64 (2 stages, both prefetched).
// Lower-triangular block band only. Stores raw fp32.
// ---------------------------------------------------------------------------
__global__ void __launch_bounds__(256) gemm_rel(const float* __restrict__ Er) {
    if (blockIdx.y > blockIdx.x) return;  // tile fully above diagonal
    extern __shared__ float sm[];
    float* As = sm;
    float* Bs = sm + 2 * GS;
    const int tid = threadIdx.x, lane = tid & 31, warp = tid >> 5;
    const int wm = warp >> 1, wn = warp & 1;
    const int rq = lane >> 2, t4 = lane & 3;
    const int l0 = blockIdx.x * 128, c0 = blockIdx.y * 128;
    const int h = blockIdx.z;
    const float* q = g_q + (size_t)h * LSEQ * HD;
    const int arow = tid >> 3, achk = (tid & 7) * 4;
    uint32_t sA = (uint32_t)__cvta_generic_to_shared(As);
    uint32_t sB = (uint32_t)__cvta_generic_to_shared(Bs);
    float acc[2][8][4] = {};

#pragma unroll
    for (int st = 0; st < 2; st++) {
        int k0 = st * 32;
#pragma unroll
        for (int p = 0; p < 4; p++) {
            int row = p * 32 + arow;
            cp16(sA + (st * GS + row * 36 + achk) * 4,
                 q + (size_t)(l0 + row) * HD + k0 + achk);
            cp16(sB + (st * GS + row * 36 + achk) * 4,
                 Er + (size_t)(c0 + row) * HD + k0 + achk);
        }
        cp_commit();
    }
    cp_wait0();
    __syncthreads();
    gemm_stage(As, Bs, acc, wm, wn, rq, t4);
    gemm_stage(As + GS, Bs + GS, acc, wm, wn, rq, t4);

#pragma unroll
    for (int mf = 0; mf < 2; mf++)
#pragma unroll
        for (int nf = 0; nf < 8; nf++)
#pragma unroll
            for (int j = 0; j < 4; j++) {
                int l = l0 + wm * 32 + mf * 16 + rq + (j >> 1) * 8;
                int m = c0 + wn * 64 + nf * 8 + 2 * t4 + (j & 1);
                g_R[((size_t)h * LSEQ + l) * LSEQ + m] = acc[mf][nf][j];
            }
}

// ---------------------------------------------------------------------------
// Kernel 3: fused flash attention + skewed rel add. BM=128 (8 warps x 16 rows),
// BN=64. Q fragments register-resident; K/V cp.async double-buffered.
// ---------------------------------------------------------------------------
__global__ void __launch_bounds__(256) flash_attn() {
    extern __shared__ float sm[];
    float* Ks = sm;                       // [2][64*68]
    float* Vs = sm + 2 * 64 * 68;         // [2][64*72]
    float* Ps = sm + 2 * 64 * 68 + 2 * 64 * 72;  // [128*68] Q staging, then P

    const int tid = threadIdx.x, lane = tid & 31, warp = tid >> 5;
    const int rq = lane >> 2, t4 = lane & 3;
    const int h = blockIdx.y;
    const int l0 = blockIdx.x * 128;
    const float* qg = g_q + (size_t)h * LSEQ * HD;
    const float* kg = g_k + (size_t)h * LSEQ * HD;
    const float* vg = g_v + (size_t)h * LSEQ * HD;
    uint32_t sK = (uint32_t)__cvta_generic_to_shared(Ks);
    uint32_t sV = (uint32_t)__cvta_generic_to_shared(Vs);
    uint32_t sP = (uint32_t)__cvta_generic_to_shared(Ps);

    // stage Q (128x64) into Ps
#pragma unroll
    for (int p = 0; p < 8; p++) {
        int cg = tid * 8 + p;
        int row = cg >> 4, c4 = (cg & 15) * 4;
        cp16(sP + (row * 68 + c4) * 4, qg + (size_t)(l0 + row) * HD + c4);
    }
    cp_commit();

    auto pre_kv = [&](int st, int kt) {
        int m0 = kt * 64;
#pragma unroll
        for (int p = 0; p < 4; p++) {
            int cg = tid * 4 + p;
            int row = cg >> 4, c4 = (cg & 15) * 4;
            cp16(sK + (st * 64 * 68 + row * 68 + c4) * 4,
                 kg + (size_t)(m0 + row) * HD + c4);
            cp16(sV + (st * 64 * 72 + row * 72 + c4) * 4,
                 vg + (size_t)(m0 + row) * HD + c4);
        }
    };
    pre_kv(0, 0);
    cp_commit();

    cp_wait1();  // Q ready (KV0 may still be in flight)
    __syncthreads();

    // Q fragments -> registers (warp-private rows of Ps)
    uint32_t qf[8][4];
#pragma unroll
    for (int ks = 0; ks < 8; ks++) {
        const float* ap = Ps + (warp * 16 + rq) * 68 + ks * 8 + t4;
        qf[ks][0] = __float_as_uint(ap[0]);
        qf[ks][1] = __float_as_uint(ap[8 * 68]);
        qf[ks][2] = __float_as_uint(ap[4]);
        qf[ks][3] = __float_as_uint(ap[8 * 68 + 4]);
    }

    const int row_lo = warp * 16 + rq;
    float Mi[2] = {-1e30f, -1e30f};
    float Si[2] = {0.f, 0.f};
    float o[8][4] = {};

    for (int kt = 0; kt < 32; kt++) {
        const int m0 = kt * 64;
        if (kt + 1 < 32) {
            pre_kv((kt + 1) & 1, kt + 1);
            cp_commit();
            cp_wait1();
        } else {
            cp_wait0();
        }
        __syncthreads();
        const float* K = Ks + (kt & 1) * 64 * 68;
        const float* V = Vs + (kt & 1) * 64 * 72;

        // S = Q @ K^T
        float s[8][4] = {};
#pragma unroll
        for (int ks = 0; ks < 8; ks++) {
            uint32_t bf[8][2];
#pragma unroll
            for (int nc = 0; nc < 8; nc++) {
                const float* bp = K + (nc * 8 + rq) * 68 + ks * 8 + t4;
                bf[nc][0] = __float_as_uint(bp[0]);
                bf[nc][1] = __float_as_uint(bp[4]);
            }
#pragma unroll
            for (int nc = 0; nc < 8; nc++)
                mma8(s[nc], qf[ks][0], qf[ks][1], qf[ks][2], qf[ks][3],
                     bf[nc][0], bf[nc][1]);
        }

        // + skewed relative scores (band tiles only)
        if (m0 <= l0 + 127) {
#pragma unroll
            for (int i = 0; i < 2; i++) {
                int l = l0 + row_lo + i * 8;
                const float* Rrow = g_R + ((size_t)h * LSEQ + l) * LSEQ + (2047 - l);
#pragma unroll
                for (int nc = 0; nc < 8; nc++) {
                    int m = m0 + nc * 8 + 2 * t4;
                    if (m <= l) s[nc][2 * i] += Rrow[m];
                    if (m + 1 <= l) s[nc][2 * i + 1] += Rrow[m + 1];
                }
            }
        }

        // online softmax (rows warp-local; quad shfl reductions)
        float mloc[2] = {-1e30f, -1e30f};
#pragma unroll
        for (int nc = 0; nc < 8; nc++) {
            mloc[0] = fmaxf(mloc[0], fmaxf(s[nc][0], s[nc][1]));
            mloc[1] = fmaxf(mloc[1], fmaxf(s[nc][2], s[nc][3]));
        }
#pragma unroll
        for (int off = 1; off < 4; off <<= 1) {
            mloc[0] = fmaxf(mloc[0], __shfl_xor_sync(0xffffffffu, mloc[0], off));
            mloc[1] = fmaxf(mloc[1], __shfl_xor_sync(0xffffffffu, mloc[1], off));
        }
        float newM[2], sc[2], lsum[2] = {0.f, 0.f};
#pragma unroll
        for (int i = 0; i < 2; i++) {
            newM[i] = fmaxf(Mi[i], mloc[i]);
            sc[i] = __expf(Mi[i] - newM[i]);
            Mi[i] = newM[i];
        }
#pragma unroll
        for (int nc = 0; nc < 8; nc++) {
            float p0 = __expf(s[nc][0] - newM[0]);
            float p1 = __expf(s[nc][1] - newM[0]);
            float p2 = __expf(s[nc][2] - newM[1]);
            float p3 = __expf(s[nc][3] - newM[1]);
            lsum[0] += p0 + p1;
            lsum[1] += p2 + p3;
            float* pp = Ps + (warp * 16 + rq) * 68 + nc * 8 + 2 * t4;
            *(float2*)pp = make_float2(to_tf32(p0), to_tf32(p1));
            *(float2*)(pp + 8 * 68) = make_float2(to_tf32(p2), to_tf32(p3));
        }
#pragma unroll
        for (int off = 1; off < 4; off <<= 1) {
            lsum[0] += __shfl_xor_sync(0xffffffffu, lsum[0], off);
            lsum[1] += __shfl_xor_sync(0xffffffffu, lsum[1], off);
        }
#pragma unroll
        for (int i = 0; i < 2; i++) Si[i] = Si[i] * sc[i] + lsum[i];
#pragma unroll
        for (int nc = 0; nc < 8; nc++) {
            o[nc][0] *= sc[0]; o[nc][1] *= sc[0];
            o[nc][2] *= sc[1]; o[nc][3] *= sc[1];
        }
        __syncwarp();  // Ps rows warp-private

        // O += P @ V
#pragma unroll
        for (int ks = 0; ks < 8; ks++) {
            const float* ap = Ps + (warp * 16 + rq) * 68 + ks * 8 + t4;
            uint32_t a0 = __float_as_uint(ap[0]);
            uint32_t a1 = __float_as_uint(ap[8 * 68]);
            uint32_t a2 = __float_as_uint(ap[4]);
            uint32_t a3 = __float_as_uint(ap[8 * 68 + 4]);
#pragma unroll
            for (int nc = 0; nc < 8; nc++) {
                const float* bp = V + (ks * 8 + t4) * 72 + nc * 8 + rq;
                mma8(o[nc], a0, a1, a2, a3,
                     __float_as_uint(bp[0]), __float_as_uint(bp[4 * 72]));
            }
        }
        __syncthreads();
    }

    float inv[2] = {1.0f / Si[0], 1.0f / Si[1]};
#pragma unroll
    for (int nc = 0; nc < 8; nc++)
#pragma unroll
        for (int j = 0; j < 4; j++) {
            int l = l0 + row_lo + (j >> 1) * 8;
            int d = nc * 8 + 2 * t4 + (j & 1);
            g_o[((size_t)h * LSEQ + l) * HD + d] = to_tf32(o[nc][j] * inv[j >> 1]);
        }
}

// ---------------------------------------------------------------------------
// Kernel 4: out = attn_out @ W_out^T + b_out (A gathered from head-major g_o)
// M=4096, N=512, K=512.
// ---------------------------------------------------------------------------
__global__ void __launch_bounds__(256) gemm_out(const float* __restrict__ Wout,
                                                const float* __restrict__ bout,
                                                float* __restrict__ out) {
    extern __shared__ float sm[];
    float* As = sm;
    float* Bs = sm + 2 * GS;
    const int tid = threadIdx.x, lane = tid & 31, warp = tid >> 5;
    const int wm = warp >> 1, wn = warp & 1;
    const int rq = lane >> 2, t4 = lane & 3;
    const int r0 = blockIdx.x * 128, c0 = blockIdx.y * 128;
    const int arow = tid >> 3, achk = (tid & 7) * 4;
    uint32_t sA = (uint32_t)__cvta_generic_to_shared(As);
    uint32_t sB = (uint32_t)__cvta_generic_to_shared(Bs);
    float acc[2][8][4] = {};

    auto prefetch = [&](int st, int kt) {
        int k0 = kt * 32;
#pragma unroll
        for (int p = 0; p < 4; p++) {
            int row = p * 32 + arow;
            int r = r0 + row;
            int l = r >> 1, b = r & 1;
            int e = k0 + achk;
            int hh = e >> 6, d = e & 63;
            cp16(sA + (st * GS + row * 36 + achk) * 4,
                 g_o + ((size_t)(b * NH + hh) * LSEQ + l) * HD + d);
            cp16(sB + (st * GS + row * 36 + achk) * 4,
                 Wout + (size_t)(c0 + row) * EMB + k0 + achk);
        }
    };

    prefetch(0, 0);
    cp_commit();
    const int nk = EMB / 32;
    for (int kt = 0; kt < nk; kt++) {
        if (kt + 1 < nk) {
            prefetch((kt + 1) & 1, kt + 1);
            cp_commit();
            cp_wait1();
        } else {
            cp_wait0();
        }
        __syncthreads();
        gemm_stage(As + (kt & 1) * GS, Bs + (kt & 1) * GS, acc, wm, wn, rq, t4);
        __syncthreads();
    }

#pragma unroll
    for (int mf = 0; mf < 2; mf++)
#pragma unroll
        for (int nf = 0; nf < 8; nf++)
#pragma unroll
            for (int j = 0; j < 4; j++) {
                int r = r0 + wm * 32 + mf * 16 + rq + (j >> 1) * 8;
                int c = c0 + wn * 64 + nf * 8 + 2 * t4 + (j & 1);
                out[(size_t)r * EMB + c] = acc[mf][nf][j] + bout[c];
            }
}

// ---------------------------------------------------------------------------
extern "C" void kernel_launch(void* const* d_in, const int* in_sizes, int n_in,
                              void* d_out, int out_size) {
    (void)in_sizes; (void)n_in; (void)out_size;
    const float* x    = (const float*)d_in[0];
    const float* Win  = (const float*)d_in[1];
    const float* bin  = (const float*)d_in[2];
    const float* Wout = (const float*)d_in[3];
    const float* bout = (const float*)d_in[4];
    const float* Er   = (const float*)d_in[5];
    float* out = (float*)d_out;

    const int gemm_smem = 4 * GS * sizeof(float);  // 73728
    const int flash_smem = (2 * 64 * 68 + 2 * 64 * 72 + 128 * 68) * sizeof(float);  // 106496

    cudaFuncSetAttribute(gemm_qkv, cudaFuncAttributeMaxDynamicSharedMemorySize, gemm_smem);
    cudaFuncSetAttribute(gemm_rel, cudaFuncAttributeMaxDynamicSharedMemorySize, gemm_smem);
    cudaFuncSetAttribute(gemm_out, cudaFuncAttributeMaxDynamicSharedMemorySize, gemm_smem);
    cudaFuncSetAttribute(flash_attn, cudaFuncAttributeMaxDynamicSharedMemorySize, flash_smem);

    gemm_qkv<<<dim3(32, 12), 256, gemm_smem>>>(x, Win, bin);
    gemm_rel<<<dim3(16, 16, 16), 256, gemm_smem>>>(Er);
    flash_attn<<<dim3(16, 16), 256, flash_smem>>>();
    gemm_out<<<dim3(32, 4), 256, gemm_smem>>>(Wout, bout, out);
}

// round 5
// speedup vs baseline: 3.1810x; 1.2798x over previous
#include <cuda_runtime.h>
#include <math.h>
#include <stdint.h>

#define LSEQ 2048
#define BATCH 2
#define EMB 512
#define NH 8
#define HD 64
#define NHEAD 16  // BATCH*NH

#define NX (LSEQ * BATCH * EMB)  // 2097152
#define NWI (3 * EMB * EMB)      // 786432
#define NWO (EMB * EMB)          // 262144
#define NER (LSEQ * HD)          // 131072

// Scratch (device globals; allocation-free per harness rules)
__device__ __align__(16) float g_q[NHEAD * LSEQ * HD];
__device__ __align__(16) float g_k[NHEAD * LSEQ * HD];
__device__ __align__(16) float g_v[NHEAD * LSEQ * HD];
__device__ __align__(16) float g_o[NHEAD * LSEQ * HD];
__device__ __align__(16) float g_R[(size_t)NHEAD * LSEQ * LSEQ + 16];  // 256 MiB
// RNA-prerounded copies of inputs (so cp.async feeds exact tf32 to mma)
__device__ __align__(16) float g_xr[NX];
__device__ __align__(16) float g_wir[NWI];
__device__ __align__(16) float g_wor[NWO];
__device__ __align__(16) float g_er[NER];

__device__ __forceinline__ float to_tf32(float x) {
    uint32_t y;
    asm("cvt.rna.tf32.f32 %0, %1;" : "=r"(y) : "f"(x));
    return __uint_as_float(y);
}

__device__ __forceinline__ void mma8(float d[4], uint32_t a0, uint32_t a1,
                                     uint32_t a2, uint32_t a3,
                                     uint32_t b0, uint32_t b1) {
    asm volatile(
        "mma.sync.aligned.m16n8k8.row.col.f32.tf32.tf32.f32 "
        "{%0,%1,%2,%3}, {%4,%5,%6,%7}, {%8,%9}, {%0,%1,%2,%3};\n"
        : "+f"(d[0]), "+f"(d[1]), "+f"(d[2]), "+f"(d[3])
        : "r"(a0), "r"(a1), "r"(a2), "r"(a3), "r"(b0), "r"(b1));
}

__device__ __forceinline__ void cp16(uint32_t dst, const void* src) {
    asm volatile("cp.async.cg.shared.global [%0], [%1], 16;\n" ::"r"(dst), "l"(src));
}
__device__ __forceinline__ void cp_commit() { asm volatile("cp.async.commit_group;\n"); }
__device__ __forceinline__ void cp_wait0() { asm volatile("cp.async.wait_group 0;\n" ::: "memory"); }
__device__ __forceinline__ void cp_wait1() { asm volatile("cp.async.wait_group 1;\n" ::: "memory"); }

// ---------------------------------------------------------------------------
// Kernel 0: RNA-preround inputs into scratch (float4 elementwise).
// ---------------------------------------------------------------------------
__global__ void __launch_bounds__(256) preround(const float4* __restrict__ x,
                                                const float4* __restrict__ Wi,
                                                const float4* __restrict__ Wo,
                                                const float4* __restrict__ Er) {
    int i = blockIdx.x * 256 + threadIdx.x;  // grid sized exactly
    float4 v;
    float4* dst;
    if (i < NX / 4) { v = x[i]; dst = (float4*)g_xr + i; }
    else if (i < (NX + NWI) / 4) { int j = i - NX / 4; v = Wi[j]; dst = (float4*)g_wir + j; }
    else if (i < (NX + NWI + NWO) / 4) { int j = i - (NX + NWI) / 4; v = Wo[j]; dst = (float4*)g_wor + j; }
    else { int j = i - (NX + NWI + NWO) / 4; v = Er[j]; dst = (float4*)g_er + j; }
    v.x = to_tf32(v.x); v.y = to_tf32(v.y); v.z = to_tf32(v.z); v.w = to_tf32(v.w);
    *dst = v;
}

#define GS (128 * 36)  // one 128-row GEMM stage (floats); stride 36 = conflict-free

// One BK=32 stage. 8 warps as 4(m)x2(n); warp tile 32 x (NF*8).
template <int NF>
__device__ __forceinline__ void gemm_stage(const float* A, const float* B,
                                           float acc[2][NF][4], int wm, int wn,
                                           int rq, int t4) {
#pragma unroll
    for (int ks = 0; ks < 4; ks++) {
        uint32_t bf[NF][2];
#pragma unroll
        for (int nf = 0; nf < NF; nf++) {
            const float* bp = B + (wn * NF * 8 + nf * 8 + rq) * 36 + ks * 8 + t4;
            bf[nf][0] = __float_as_uint(bp[0]);
            bf[nf][1] = __float_as_uint(bp[4]);
        }
#pragma unroll
        for (int mf = 0; mf < 2; mf++) {
            const float* ap = A + (wm * 32 + mf * 16 + rq) * 36 + ks * 8 + t4;
            uint32_t a0 = __float_as_uint(ap[0]);
            uint32_t a1 = __float_as_uint(ap[8 * 36]);
            uint32_t a2 = __float_as_uint(ap[4]);
            uint32_t a3 = __float_as_uint(ap[8 * 36 + 4]);
#pragma unroll
            for (int nf = 0; nf < NF; nf++)
                mma8(acc[mf][nf], a0, a1, a2, a3, bf[nf][0], bf[nf][1]);
        }
    }
}

// ---------------------------------------------------------------------------
// Kernel 1: qkv = xr @ Wir^T + b -> scatter head-major (q scaled), tf32-rounded.
// ---------------------------------------------------------------------------
__global__ void __launch_bounds__(256, 2) gemm_qkv(const float* __restrict__ bias) {
    extern __shared__ float sm[];
    float* As = sm;
    float* Bs = sm + 2 * GS;
    const int tid = threadIdx.x, lane = tid & 31, warp = tid >> 5;
    const int wm = warp >> 1, wn = warp & 1;
    const int rq = lane >> 2, t4 = lane & 3;
    const int r0 = blockIdx.x * 128, c0 = blockIdx.y * 128;
    const int arow = tid >> 3, achk = (tid & 7) * 4;
    uint32_t sA = (uint32_t)__cvta_generic_to_shared(As);
    uint32_t sB = (uint32_t)__cvta_generic_to_shared(Bs);
    float acc[2][8][4] = {};

    auto prefetch = [&](int st, int kt) {
        int k0 = kt * 32;
#pragma unroll
        for (int p = 0; p < 4; p++) {
            int row = p * 32 + arow;
            cp16(sA + (st * GS + row * 36 + achk) * 4,
                 g_xr + (size_t)(r0 + row) * EMB + k0 + achk);
            cp16(sB + (st * GS + row * 36 + achk) * 4,
                 g_wir + (size_t)(c0 + row) * EMB + k0 + achk);
        }
    };

    prefetch(0, 0);
    cp_commit();
    const int nk = EMB / 32;
    for (int kt = 0; kt < nk; kt++) {
        if (kt + 1 < nk) {
            prefetch((kt + 1) & 1, kt + 1);
            cp_commit();
            cp_wait1();
        } else {
            cp_wait0();
        }
        __syncthreads();
        gemm_stage<8>(As + (kt & 1) * GS, Bs + (kt & 1) * GS, acc, wm, wn, rq, t4);
        __syncthreads();
    }

#pragma unroll
    for (int mf = 0; mf < 2; mf++)
#pragma unroll
        for (int nf = 0; nf < 8; nf++)
#pragma unroll
            for (int j = 0; j < 4; j++) {
                int r = r0 + wm * 32 + mf * 16 + rq + (j >> 1) * 8;
                int c = c0 + wn * 64 + nf * 8 + 2 * t4 + (j & 1);
                float val = acc[mf][nf][j] + bias[c];
                int l = r >> 1, b = r & 1;
                int part = c >> 9;
                int cc = c & 511;
                int h = cc >> 6, d = cc & 63;
                size_t idx = ((size_t)(b * NH + h) * LSEQ + l) * HD + d;
                if (part == 0) g_q[idx] = to_tf32(val) * 0.125f;
                else if (part == 1) g_k[idx] = to_tf32(val);
                else g_v[idx] = to_tf32(val);
            }
}

// ---------------------------------------------------------------------------
// Kernel 2: R[h,l,m] = q[h,l,:] . er[m,:]. Lower-triangular tile band only.
// ---------------------------------------------------------------------------
__global__ void __launch_bounds__(256, 2) gemm_rel() {
    if (blockIdx.y > blockIdx.x) return;
    extern __shared__ float sm[];
    float* As = sm;
    float* Bs = sm + 2 * GS;
    const int tid = threadIdx.x, lane = tid & 31, warp = tid >> 5;
    const int wm = warp >> 1, wn = warp & 1;
    const int rq = lane >> 2, t4 = lane & 3;
    const int l0 = blockIdx.x * 128, c0 = blockIdx.y * 128;
    const int h = blockIdx.z;
    const float* q = g_q + (size_t)h * LSEQ * HD;
    const int arow = tid >> 3, achk = (tid & 7) * 4;
    uint32_t sA = (uint32_t)__cvta_generic_to_shared(As);
    uint32_t sB = (uint32_t)__cvta_generic_to_shared(Bs);
    float acc[2][8][4] = {};

#pragma unroll
    for (int st = 0; st < 2; st++) {
        int k0 = st * 32;
#pragma unroll
        for (int p = 0; p < 4; p++) {
            int row = p * 32 + arow;
            cp16(sA + (st * GS + row * 36 + achk) * 4,
                 q + (size_t)(l0 + row) * HD + k0 + achk);
            cp16(sB + (st * GS + row * 36 + achk) * 4,
                 g_er + (size_t)(c0 + row) * HD + k0 + achk);
        }
        cp_commit();
    }
    cp_wait0();
    __syncthreads();
    gemm_stage<8>(As, Bs, acc, wm, wn, rq, t4);
    gemm_stage<8>(As + GS, Bs + GS, acc, wm, wn, rq, t4);

#pragma unroll
    for (int mf = 0; mf < 2; mf++)
#pragma unroll
        for (int nf = 0; nf < 8; nf++)
#pragma unroll
            for (int j = 0; j < 4; j++) {
                int l = l0 + wm * 32 + mf * 16 + rq + (j >> 1) * 8;
                int m = c0 + wn * 64 + nf * 8 + 2 * t4 + (j & 1);
                g_R[((size_t)h * LSEQ + l) * LSEQ + m] = acc[mf][nf][j];
            }
}

// ---------------------------------------------------------------------------
// Kernel 3: fused flash attention + skewed rel add. BM=128 (8 warps x 16 rows),
// BN=64. Q frags in registers; K/V cp.async x2; P converted C->A frag via shfl
// (no smem round trip). smem = 70 KB -> 2+ blocks/SM.
// ---------------------------------------------------------------------------
#define FS_K (64 * 68)
#define FS_V (64 * 72)
__global__ void __launch_bounds__(256, 2) flash_attn() {
    extern __shared__ float sm[];
    float* Ks = sm;               // [2][64*68]; also Q staging (128*68 fits in 2*FS_K)
    float* Vs = sm + 2 * FS_K;    // [2][64*72]

    const int tid = threadIdx.x, lane = tid & 31, warp = tid >> 5;
    const int rq = lane >> 2, t4 = lane & 3;
    const int h = blockIdx.y;
    const int l0 = blockIdx.x * 128;
    const float* qg = g_q + (size_t)h * LSEQ * HD;
    const float* kg = g_k + (size_t)h * LSEQ * HD;
    const float* vg = g_v + (size_t)h * LSEQ * HD;
    uint32_t sK = (uint32_t)__cvta_generic_to_shared(Ks);
    uint32_t sV = (uint32_t)__cvta_generic_to_shared(Vs);

    // stage Q (128x64) into the K region, extract fragments, then release
#pragma unroll
    for (int p = 0; p < 8; p++) {
        int cg = tid * 8 + p;
        int row = cg >> 4, c4 = (cg & 15) * 4;
        cp16(sK + (row * 68 + c4) * 4, qg + (size_t)(l0 + row) * HD + c4);
    }
    cp_commit();
    cp_wait0();
    __syncthreads();

    uint32_t qf[8][4];
#pragma unroll
    for (int ks = 0; ks < 8; ks++) {
        const float* ap = Ks + (warp * 16 + rq) * 68 + ks * 8 + t4;
        qf[ks][0] = __float_as_uint(ap[0]);
        qf[ks][1] = __float_as_uint(ap[8 * 68]);
        qf[ks][2] = __float_as_uint(ap[4]);
        qf[ks][3] = __float_as_uint(ap[8 * 68 + 4]);
    }
    __syncthreads();  // everyone done reading Q before KV prefetch overwrites

    auto pre_kv = [&](int st, int kt) {
        int m0 = kt * 64;
#pragma unroll
        for (int p = 0; p < 4; p++) {
            int cg = tid * 4 + p;
            int row = cg >> 4, c4 = (cg & 15) * 4;
            cp16(sK + (st * FS_K + row * 68 + c4) * 4,
                 kg + (size_t)(m0 + row) * HD + c4);
            cp16(sV + (st * FS_V + row * 72 + c4) * 4,
                 vg + (size_t)(m0 + row) * HD + c4);
        }
    };
    pre_kv(0, 0);
    cp_commit();

    const int row_lo = warp * 16 + rq;
    const int src1 = (lane & ~3) | (t4 >> 1);
    const int src2 = src1 + 2;
    const bool odd = t4 & 1;
    float Mi[2] = {-1e30f, -1e30f};
    float Si[2] = {0.f, 0.f};
    float o[8][4] = {};

    for (int kt = 0; kt < 32; kt++) {
        const int m0 = kt * 64;
        if (kt + 1 < 32) {
            pre_kv((kt + 1) & 1, kt + 1);
            cp_commit();
            cp_wait1();
        } else {
            cp_wait0();
        }
        __syncthreads();
        const float* K = Ks + (kt & 1) * FS_K;
        const float* V = Vs + (kt & 1) * FS_V;

        // S = Q @ K^T
        float s[8][4] = {};
#pragma unroll
        for (int ks = 0; ks < 8; ks++) {
            uint32_t bf[8][2];
#pragma unroll
            for (int nc = 0; nc < 8; nc++) {
                const float* bp = K + (nc * 8 + rq) * 68 + ks * 8 + t4;
                bf[nc][0] = __float_as_uint(bp[0]);
                bf[nc][1] = __float_as_uint(bp[4]);
            }
#pragma unroll
            for (int nc = 0; nc < 8; nc++)
                mma8(s[nc], qf[ks][0], qf[ks][1], qf[ks][2], qf[ks][3],
                     bf[nc][0], bf[nc][1]);
        }

        // + skewed relative scores (band tiles only)
        if (m0 <= l0 + 127) {
#pragma unroll
            for (int i = 0; i < 2; i++) {
                int l = l0 + row_lo + i * 8;
                const float* Rrow = g_R + ((size_t)h * LSEQ + l) * LSEQ + (2047 - l);
#pragma unroll
                for (int nc = 0; nc < 8; nc++) {
                    int m = m0 + nc * 8 + 2 * t4;
                    if (m <= l) s[nc][2 * i] += Rrow[m];
                    if (m + 1 <= l) s[nc][2 * i + 1] += Rrow[m + 1];
                }
            }
        }

        // online softmax (rows warp-local; quad shfl reductions)
        float mloc[2] = {-1e30f, -1e30f};
#pragma unroll
        for (int nc = 0; nc < 8; nc++) {
            mloc[0] = fmaxf(mloc[0], fmaxf(s[nc][0], s[nc][1]));
            mloc[1] = fmaxf(mloc[1], fmaxf(s[nc][2], s[nc][3]));
        }
#pragma unroll
        for (int off = 1; off < 4; off <<= 1) {
            mloc[0] = fmaxf(mloc[0], __shfl_xor_sync(0xffffffffu, mloc[0], off));
            mloc[1] = fmaxf(mloc[1], __shfl_xor_sync(0xffffffffu, mloc[1], off));
        }
        float newM[2], sc[2], lsum[2] = {0.f, 0.f};
#pragma unroll
        for (int i = 0; i < 2; i++) {
            newM[i] = fmaxf(Mi[i], mloc[i]);
            sc[i] = __expf(Mi[i] - newM[i]);
            Mi[i] = newM[i];
        }
        // P = exp(S - M) kept in the C-fragment registers (s), tf32-rounded
#pragma unroll
        for (int nc = 0; nc < 8; nc++) {
            float p0 = __expf(s[nc][0] - newM[0]);
            float p1 = __expf(s[nc][1] - newM[0]);
            float p2 = __expf(s[nc][2] - newM[1]);
            float p3 = __expf(s[nc][3] - newM[1]);
            lsum[0] += p0 + p1;
            lsum[1] += p2 + p3;
            s[nc][0] = to_tf32(p0); s[nc][1] = to_tf32(p1);
            s[nc][2] = to_tf32(p2); s[nc][3] = to_tf32(p3);
        }
#pragma unroll
        for (int off = 1; off < 4; off <<= 1) {
            lsum[0] += __shfl_xor_sync(0xffffffffu, lsum[0], off);
            lsum[1] += __shfl_xor_sync(0xffffffffu, lsum[1], off);
        }
#pragma unroll
        for (int i = 0; i < 2; i++) Si[i] = Si[i] * sc[i] + lsum[i];
#pragma unroll
        for (int nc = 0; nc < 8; nc++) {
            o[nc][0] *= sc[0]; o[nc][1] *= sc[0];
            o[nc][2] *= sc[1]; o[nc][3] *= sc[1];
        }

        // O += P @ V : convert P C-frag -> A-frag via quad shuffles
#pragma unroll
        for (int g = 0; g < 8; g++) {
            float v00 = __shfl_sync(0xffffffffu, s[g][0], src1);
            float v01 = __shfl_sync(0xffffffffu, s[g][1], src1);
            float v02 = __shfl_sync(0xffffffffu, s[g][2], src1);
            float v03 = __shfl_sync(0xffffffffu, s[g][3], src1);
            float w00 = __shfl_sync(0xffffffffu, s[g][0], src2);
            float w01 = __shfl_sync(0xffffffffu, s[g][1], src2);
            float w02 = __shfl_sync(0xffffffffu, s[g][2], src2);
            float w03 = __shfl_sync(0xffffffffu, s[g][3], src2);
            uint32_t a0 = __float_as_uint(odd ? v01 : v00);
            uint32_t a1 = __float_as_uint(odd ? v03 : v02);
            uint32_t a2 = __float_as_uint(odd ? w01 : w00);
            uint32_t a3 = __float_as_uint(odd ? w03 : w02);
#pragma unroll
            for (int nc = 0; nc < 8; nc++) {
                const float* bp = V + (g * 8 + t4) * 72 + nc * 8 + rq;
                mma8(o[nc], a0, a1, a2, a3,
                     __float_as_uint(bp[0]), __float_as_uint(bp[4 * 72]));
            }
        }
        __syncthreads();
    }

    float inv[2] = {1.0f / Si[0], 1.0f / Si[1]};
#pragma unroll
    for (int nc = 0; nc < 8; nc++)
#pragma unroll
        for (int j = 0; j < 4; j++) {
            int l = l0 + row_lo + (j >> 1) * 8;
            int d = nc * 8 + 2 * t4 + (j & 1);
            g_o[((size_t)h * LSEQ + l) * HD + d] = to_tf32(o[nc][j] * inv[j >> 1]);
        }
}

// ---------------------------------------------------------------------------
// Kernel 4: out = attn_out @ Wor^T + b. BM=128, BN=64 (grid 256 for occupancy).
// ---------------------------------------------------------------------------
__global__ void __launch_bounds__(256, 2) gemm_out(const float* __restrict__ bout,
                                                   float* __restrict__ out) {
    extern __shared__ float sm[];
    float* As = sm;                 // [2][128*36]
    float* Bs = sm + 2 * GS;        // [2][64*36]
    const int tid = threadIdx.x, lane = tid & 31, warp = tid >> 5;
    const int wm = warp >> 1, wn = warp & 1;
    const int rq = lane >> 2, t4 = lane & 3;
    const int r0 = blockIdx.x * 128, c0 = blockIdx.y * 64;
    const int arow = tid >> 3, achk = (tid & 7) * 4;
    uint32_t sA = (uint32_t)__cvta_generic_to_shared(As);
    uint32_t sB = (uint32_t)__cvta_generic_to_shared(Bs);
    const int BGS = 64 * 36;
    float acc[2][4][4] = {};

    auto prefetch = [&](int st, int kt) {
        int k0 = kt * 32;
#pragma unroll
        for (int p = 0; p < 4; p++) {
            int row = p * 32 + arow;
            int r = r0 + row;
            int l = r >> 1, b = r & 1;
            int e = k0 + achk;
            int hh = e >> 6, d = e & 63;
            cp16(sA + (st * GS + row * 36 + achk) * 4,
                 g_o + ((size_t)(b * NH + hh) * LSEQ + l) * HD + d);
        }
#pragma unroll
        for (int p = 0; p < 2; p++) {
            int row = p * 32 + arow;
            cp16(sB + (st * BGS + row * 36 + achk) * 4,
                 g_wor + (size_t)(c0 + row) * EMB + k0 + achk);
        }
    };

    prefetch(0, 0);
    cp_commit();
    const int nk = EMB / 32;
    for (int kt = 0; kt < nk; kt++) {
        if (kt + 1 < nk) {
            prefetch((kt + 1) & 1, kt + 1);
            cp_commit();
            cp_wait1();
        } else {
            cp_wait0();
        }
        __syncthreads();
        gemm_stage<4>(As + (kt & 1) * GS, Bs + (kt & 1) * BGS, acc, wm, wn, rq, t4);
        __syncthreads();
    }

#pragma unroll
    for (int mf = 0; mf < 2; mf++)
#pragma unroll
        for (int nf = 0; nf < 4; nf++)
#pragma unroll
            for (int j = 0; j < 4; j++) {
                int r = r0 + wm * 32 + mf * 16 + rq + (j >> 1) * 8;
                int c = c0 + wn * 32 + nf * 8 + 2 * t4 + (j & 1);
                out[(size_t)r * EMB + c] = acc[mf][nf][j] + bout[c];
            }
}

// ---------------------------------------------------------------------------
extern "C" void kernel_launch(void* const* d_in, const int* in_sizes, int n_in,
                              void* d_out, int out_size) {
    (void)in_sizes; (void)n_in; (void)out_size;
    const float* x    = (const float*)d_in[0];
    const float* Win  = (const float*)d_in[1];
    const float* bin  = (const float*)d_in[2];
    const float* Wout = (const float*)d_in[3];
    const float* bout = (const float*)d_in[4];
    const float* Er   = (const float*)d_in[5];
    float* out = (float*)d_out;

    const int gemm_smem = 4 * GS * sizeof(float);                      // 73728
    const int out_smem = (2 * GS + 2 * 64 * 36) * sizeof(float);       // 55296
    const int flash_smem = (2 * FS_K + 2 * FS_V) * sizeof(float);      // 71680

    cudaFuncSetAttribute(gemm_qkv, cudaFuncAttributeMaxDynamicSharedMemorySize, gemm_smem);
    cudaFuncSetAttribute(gemm_rel, cudaFuncAttributeMaxDynamicSharedMemorySize, gemm_smem);
    cudaFuncSetAttribute(gemm_out, cudaFuncAttributeMaxDynamicSharedMemorySize, out_smem);
    cudaFuncSetAttribute(flash_attn, cudaFuncAttributeMaxDynamicSharedMemorySize, flash_smem);

    preround<<<(NX + NWI + NWO + NER) / 4 / 256, 256>>>(
        (const float4*)x, (const float4*)Win, (const float4*)Wout, (const float4*)Er);
    gemm_qkv<<<dim3(32, 12), 256, gemm_smem>>>(bin);
    gemm_rel<<<dim3(16, 16, 16), 256, gemm_smem>>>();
    flash_attn<<<dim3(16, 16), 256, flash_smem>>>();
    gemm_out<<<dim3(32, 8), 256, out_smem>>>(bout, out);
}